// round 11
// baseline (speedup 1.0000x reference)
#include <cuda_runtime.h>
#include <cuda_bf16.h>
#include <cstdint>

#define N_VOX 200000
#define PP    65536
#define EPSV  1e-5f
#define TILES 4

// ---- scratch (__device__ globals; allocation-free rule) ----
__device__ float g_h1[(size_t)N_VOX * 64];
__device__ float g_h2[(size_t)N_VOX * 64];
__device__ __nv_bfloat16 g_wb[27 * 9216];  // [27][hi 64x72 | lo 64x72] bf16 row-major [k][n]
__device__ float g_stats[256];
__device__ float g_coef[256];

#define RED2(p, a, b) \
    asm volatile("red.global.add.v2.f32 [%0], {%1,%2};" \
                 :: "l"(p), "f"(a), "f"(b) : "memory")

#define LDMB2T(r, addr) \
    asm volatile("ldmatrix.sync.aligned.m8n8.x2.trans.shared.b16 {%0,%1}, [%2];" \
                 : "=r"((r)[0]), "=r"((r)[1]) : "r"(addr))

#define MMA16816(d, a, b) \
    asm volatile("mma.sync.aligned.m16n8k16.row.col.f32.bf16.bf16.f32 " \
                 "{%0,%1,%2,%3},{%4,%5,%6,%7},{%8,%9},{%0,%1,%2,%3};" \
                 : "+f"((d)[0]), "+f"((d)[1]), "+f"((d)[2]), "+f"((d)[3]) \
                 : "r"((a)[0]), "r"((a)[1]), "r"((a)[2]), "r"((a)[3]), \
                   "r"((b)[0]), "r"((b)[1]))

// bf16 hi/lo split of a float2, packed as bf16x2 regs
__device__ __forceinline__ void split2(float2 v, uint32_t& hi, uint32_t& lo) {
    __nv_bfloat162 h = __float22bfloat162_rn(v);
    float2 hf = __bfloat1622float2(h);
    __nv_bfloat162 l = __float22bfloat162_rn(make_float2(v.x - hf.x, v.y - hf.y));
    hi = *reinterpret_cast<uint32_t*>(&h);
    lo = *reinterpret_cast<uint32_t*>(&l);
}

// smem: W tile only: [hi 64x72 | lo 64x72] bf16 row-major [k][n], 18432 B
#define DSMEM_BYTES 18432

// ---------------------------------------------------------------------------
// A fragments built DIRECTLY from global (documented m16n8k16 A layout:
// each 32-bit reg = 2 consecutive k-elements of one row). No A smem at all.
// ---------------------------------------------------------------------------
template <bool SCATTER, bool FUSE_BN>
__global__ __launch_bounds__(128, 4)
void conv_mma_kernel(const float* __restrict__ x,
                     const __nv_bfloat16* __restrict__ wb,
                     const int* __restrict__ in_map,
                     const int* __restrict__ out_map,
                     float* __restrict__ H)
{
    extern __shared__ char sm[];

    const int t    = threadIdx.x;
    const int w    = t >> 5;
    const int lane = t & 31;

    const int ky = SCATTER ? blockIdx.y : 0;
    const int o  = SCATTER ? (ky < 13 ? ky : ky + 1) : 13;

    // Stage W_o once per block (hi+lo, stride 72 = 144B rows, 18432 B)
    {
        const uint4* src = reinterpret_cast<const uint4*>(wb + (size_t)o * 9216);
        uint4*       dst = reinterpret_cast<uint4*>(sm);
#pragma unroll
        for (int i = 0; i < 9; i++) dst[t + i * 128] = src[t + i * 128];
    }
    __syncthreads();   // only block barrier

    const uint32_t aW = (uint32_t)__cvta_generic_to_shared(sm);
    const int rq    = lane >> 2;     // 0..7  (fragment row group)
    const int cpair = lane & 3;      // fragment col pair

    const float2* x2 = reinterpret_cast<const float2*>(x);

    for (int tt = 0; tt < TILES; tt++) {
        const int base = (blockIdx.x * TILES + tt) * 128;
        if (!SCATTER && base >= N_VOX) break;

        int myrow, myorow;
        if (SCATTER) {
            const size_t kbase = (size_t)ky * PP + base;
            if (__ldg(&in_map[kbase]) >= N_VOX) break;   // tail-packed sentinels
            myrow  = __ldg(&in_map[kbase + t]);
            myorow = __ldg(&out_map[kbase + t]);
        }

        float acc[2][8][4];
#pragma unroll
        for (int mt = 0; mt < 2; mt++)
#pragma unroll
            for (int nt = 0; nt < 8; nt++)
#pragma unroll
                for (int i = 0; i < 4; i++) acc[mt][nt][i] = 0.f;

#pragma unroll
        for (int ks = 0; ks < 4; ks++) {
            // ---- A: gather float2s straight into fragment slots ----
            // cols: c0 = 2*cpair + 16*ks (float2 idx cc0), c1 = c0+8 (cc0+4)
            const int cc0 = cpair + ks * 8;
            float2 f[2][4];   // [mt][a0,a1,a2,a3 source float2]
#pragma unroll
            for (int mt = 0; mt < 2; mt++) {
                const int r0l = mt * 16 + rq;
                const int r1l = r0l + 8;
                int row0, row1;
                if (SCATTER) {
                    row0 = __shfl_sync(0xffffffffu, myrow, r0l);
                    row1 = __shfl_sync(0xffffffffu, myrow, r1l);
                } else {
                    row0 = base + w * 32 + r0l;
                    row1 = base + w * 32 + r1l;
                }
                const float2 z = make_float2(0.f, 0.f);
                f[mt][0] = row0 < N_VOX ? x2[(size_t)row0 * 32 + cc0]     : z;
                f[mt][1] = row1 < N_VOX ? x2[(size_t)row1 * 32 + cc0]     : z;
                f[mt][2] = row0 < N_VOX ? x2[(size_t)row0 * 32 + cc0 + 4] : z;
                f[mt][3] = row1 < N_VOX ? x2[(size_t)row1 * 32 + cc0 + 4] : z;
            }

            // ---- B: ldmatrix x2.trans from W smem (row-major [k][n]) ----
            uint32_t bh[8][2], bl[8][2];
            const uint32_t brow = aW + (ks * 16 + (lane & 15)) * 144;
#pragma unroll
            for (int nt = 0; nt < 8; nt++) {
                LDMB2T(bh[nt], brow + nt * 16);
                LDMB2T(bl[nt], brow + nt * 16 + 9216);
            }

            // ---- optional fused BN1+ReLU (coefs: 4 hot float2 loads) ----
            if (FUSE_BN) {
                const int c0 = cpair * 2 + ks * 16;
                float2 sc0 = *reinterpret_cast<const float2*>(&g_coef[c0]);
                float2 sb0 = *reinterpret_cast<const float2*>(&g_coef[64 + c0]);
                float2 sc1 = *reinterpret_cast<const float2*>(&g_coef[c0 + 8]);
                float2 sb1 = *reinterpret_cast<const float2*>(&g_coef[64 + c0 + 8]);
#pragma unroll
                for (int mt = 0; mt < 2; mt++) {
#pragma unroll
                    for (int i = 0; i < 2; i++) {   // a0,a1 use c0; a2,a3 use c1
                        f[mt][i].x     = fmaxf(fmaf(f[mt][i].x,     sc0.x, sb0.x), 0.f);
                        f[mt][i].y     = fmaxf(fmaf(f[mt][i].y,     sc0.y, sb0.y), 0.f);
                        f[mt][i + 2].x = fmaxf(fmaf(f[mt][i + 2].x, sc1.x, sb1.x), 0.f);
                        f[mt][i + 2].y = fmaxf(fmaf(f[mt][i + 2].y, sc1.y, sb1.y), 0.f);
                    }
                }
            }

            // ---- split + 3-pass MMA ----
#pragma unroll
            for (int mt = 0; mt < 2; mt++) {
                uint32_t ah[4], al[4];
                split2(f[mt][0], ah[0], al[0]);
                split2(f[mt][1], ah[1], al[1]);
                split2(f[mt][2], ah[2], al[2]);
                split2(f[mt][3], ah[3], al[3]);
#pragma unroll
                for (int nt = 0; nt < 8; nt++) {
                    MMA16816(acc[mt][nt], ah, bh[nt]);
                    MMA16816(acc[mt][nt], ah, bl[nt]);
                    MMA16816(acc[mt][nt], al, bh[nt]);
                }
            }
        }

        // ---- Epilogue DIRECT from acc regs ----
        // {c0,c1} -> row l/4, cols 2(l%4)+{0,1}; {c2,c3} -> row l/4+8
        const int cb = cpair * 2;
#pragma unroll
        for (int mt = 0; mt < 2; mt++) {
            const int rl1 = mt * 16 + rq;
            const int rl2 = rl1 + 8;
            int o1, o2;
            if (SCATTER) {
                o1 = __shfl_sync(0xffffffffu, myorow, rl1);
                o2 = __shfl_sync(0xffffffffu, myorow, rl2);
            } else {
                o1 = base + w * 32 + rl1;
                o2 = base + w * 32 + rl2;
            }
            if (o1 < N_VOX) {
                float* d = H + (size_t)o1 * 64 + cb;
                if (SCATTER) {
#pragma unroll
                    for (int nt = 0; nt < 8; nt++)
                        RED2(d + nt * 8, acc[mt][nt][0], acc[mt][nt][1]);
                } else {
#pragma unroll
                    for (int nt = 0; nt < 8; nt++)
                        *reinterpret_cast<float2*>(d + nt * 8) =
                            make_float2(acc[mt][nt][0], acc[mt][nt][1]);
                }
            }
            if (o2 < N_VOX) {
                float* d = H + (size_t)o2 * 64 + cb;
                if (SCATTER) {
#pragma unroll
                    for (int nt = 0; nt < 8; nt++)
                        RED2(d + nt * 8, acc[mt][nt][2], acc[mt][nt][3]);
                } else {
#pragma unroll
                    for (int nt = 0; nt < 8; nt++)
                        *reinterpret_cast<float2*>(d + nt * 8) =
                            make_float2(acc[mt][nt][2], acc[mt][nt][3]);
                }
            }
        }
    }
}

// ---------------------------------------------------------------------------
// W prep: bf16 hi/lo split into padded [27][2][64(k)][72(n)]
__global__ void wprep_kernel(const float* __restrict__ W)
{
    const int o = blockIdx.x;
    const int t = threadIdx.x;   // 128
    for (int idx = t; idx < 4608; idx += 128) {
        const int k = idx / 72, n = idx % 72;
        float v = (n < 64) ? W[(size_t)o * 4096 + k * 64 + n] : 0.f;
        __nv_bfloat16 hi = __float2bfloat16(v);
        __nv_bfloat16 lo = __float2bfloat16(v - __bfloat162float(hi));
        g_wb[(size_t)o * 9216 + idx]        = hi;
        g_wb[(size_t)o * 9216 + 4608 + idx] = lo;
    }
}

// ---------------------------------------------------------------------------
__global__ void zero_stats_kernel() { g_stats[threadIdx.x] = 0.f; }

__global__ void stats_kernel(const float* __restrict__ h, int statoff)
{
    const int t = threadIdx.x;          // 256
    const int ch = t & 63;
    const int g  = t >> 6;
    float s = 0.f, sq = 0.f;
#pragma unroll 8
    for (int row = blockIdx.x * 4 + g; row < N_VOX; row += gridDim.x * 4) {
        float v = h[(size_t)row * 64 + ch];
        s += v; sq = fmaf(v, v, sq);
    }
    __shared__ float sh[2][4][64];
    sh[0][g][ch] = s;
    sh[1][g][ch] = sq;
    __syncthreads();
    if (t < 64) {
        float ss = sh[0][0][t] + sh[0][1][t] + sh[0][2][t] + sh[0][3][t];
        atomicAdd(&g_stats[statoff + t], ss);
    } else if (t < 128) {
        int c = t - 64;
        float qq = sh[1][0][c] + sh[1][1][c] + sh[1][2][c] + sh[1][3][c];
        atomicAdd(&g_stats[statoff + 64 + c], qq);
    }
}

__global__ void finalize_stats_kernel(const float* __restrict__ gamma,
                                      const float* __restrict__ beta,
                                      int statoff, int coefoff)
{
    const int c = threadIdx.x;  // 64
    const float inv_n = 1.0f / (float)N_VOX;
    float mu  = g_stats[statoff + c] * inv_n;
    float var = g_stats[statoff + 64 + c] * inv_n - mu * mu;
    float sc  = gamma[c] * rsqrtf(var + EPSV);
    g_coef[coefoff + c]      = sc;
    g_coef[coefoff + 64 + c] = beta[c] - mu * sc;
}

// out = relu(bn2(h2) + x)
__global__ void final_kernel(const float* __restrict__ h2,
                             const float* __restrict__ x,
                             float* __restrict__ out, int coefoff)
{
    int kk = blockIdx.x * blockDim.x + threadIdx.x;
    if (kk >= N_VOX * 16) return;
    int cb = (kk & 15) * 4;
    float4 v = reinterpret_cast<const float4*>(h2)[kk];
    float4 r = reinterpret_cast<const float4*>(x)[kk];
    float s0 = g_coef[coefoff + cb + 0], b0 = g_coef[coefoff + 64 + cb + 0];
    float s1 = g_coef[coefoff + cb + 1], b1 = g_coef[coefoff + 64 + cb + 1];
    float s2 = g_coef[coefoff + cb + 2], b2 = g_coef[coefoff + 64 + cb + 2];
    float s3 = g_coef[coefoff + cb + 3], b3 = g_coef[coefoff + 64 + cb + 3];
    v.x = fmaxf(fmaf(v.x, s0, b0) + r.x, 0.f);
    v.y = fmaxf(fmaf(v.y, s1, b1) + r.y, 0.f);
    v.z = fmaxf(fmaf(v.z, s2, b2) + r.z, 0.f);
    v.w = fmaxf(fmaf(v.w, s3, b3) + r.w, 0.f);
    reinterpret_cast<float4*>(out)[kk] = v;
}

// ---------------------------------------------------------------------------
extern "C" void kernel_launch(void* const* d_in, const int* in_sizes, int n_in,
                              void* d_out, int out_size)
{
    const float* x      = (const float*)d_in[0];
    const float* W1     = (const float*)d_in[1];
    const float* gamma1 = (const float*)d_in[2];
    const float* beta1  = (const float*)d_in[3];
    const float* W2     = (const float*)d_in[4];
    const float* gamma2 = (const float*)d_in[5];
    const float* beta2  = (const float*)d_in[6];
    const int*   in_map = (const int*)d_in[7];
    const int*   out_map= (const int*)d_in[8];
    float*       out    = (float*)d_out;

    float* h1;  cudaGetSymbolAddress((void**)&h1, g_h1);
    float* h2;  cudaGetSymbolAddress((void**)&h2, g_h2);
    __nv_bfloat16* wb;  cudaGetSymbolAddress((void**)&wb, g_wb);

    const dim3 scat_grid(PP / (128 * TILES), 26);
    const int  center_blocks = (N_VOX + 128 * TILES - 1) / (128 * TILES);
    const int  ew_blocks     = (N_VOX * 16 + 255) / 256;

    zero_stats_kernel<<<1, 256>>>();

    // conv1 (raw x)
    wprep_kernel<<<27, 128>>>(W1);
    conv_mma_kernel<false, false><<<center_blocks, 128, DSMEM_BYTES>>>(x, wb, nullptr, nullptr, h1);
    conv_mma_kernel<true,  false><<<scat_grid,     128, DSMEM_BYTES>>>(x, wb, in_map, out_map, h1);
    stats_kernel<<<1024, 256>>>(h1, 0);
    finalize_stats_kernel<<<1, 64>>>(gamma1, beta1, 0, 0);

    // conv2: BN1+ReLU fused into the gather (h1 stays raw)
    wprep_kernel<<<27, 128>>>(W2);
    conv_mma_kernel<false, true><<<center_blocks, 128, DSMEM_BYTES>>>(h1, wb, nullptr, nullptr, h2);
    conv_mma_kernel<true,  true><<<scat_grid,     128, DSMEM_BYTES>>>(h1, wb, in_map, out_map, h2);
    stats_kernel<<<1024, 256>>>(h2, 128);
    finalize_stats_kernel<<<1, 64>>>(gamma2, beta2, 128, 128);

    // bn2 + residual + relu -> d_out
    final_kernel<<<ew_blocks, 256>>>(h2, x, out, 128);
}

// round 12
// speedup vs baseline: 1.1328x; 1.1328x over previous
#include <cuda_runtime.h>
#include <cuda_bf16.h>
#include <cstdint>

#define N_VOX 200000
#define PP    65536
#define EPSV  1e-5f
#define TILES 4

// ---- scratch (__device__ globals; allocation-free rule) ----
__device__ float g_h1[(size_t)N_VOX * 64];
__device__ float g_h2[(size_t)N_VOX * 64];
__device__ __nv_bfloat16 g_wb[27 * 9216];  // [27][hi 64x72 | lo 64x72] bf16 row-major [k][n]
__device__ float g_stats[256];
__device__ float g_coef[256];

#define RED2(p, a, b) \
    asm volatile("red.global.add.v2.f32 [%0], {%1,%2};" \
                 :: "l"(p), "f"(a), "f"(b) : "memory")

#define LDMA4(r, addr) \
    asm volatile("ldmatrix.sync.aligned.m8n8.x4.shared.b16 {%0,%1,%2,%3}, [%4];" \
                 : "=r"((r)[0]), "=r"((r)[1]), "=r"((r)[2]), "=r"((r)[3]) : "r"(addr))

// x4.trans: lanes 0-15 address hi tiles (k16), lanes 16-31 address lo tiles
// -> one instruction yields bh{0,1} (regs 0,1) and bl{0,1} (regs 2,3).
#define LDMB4T(r, addr) \
    asm volatile("ldmatrix.sync.aligned.m8n8.x4.trans.shared.b16 {%0,%1,%2,%3}, [%4];" \
                 : "=r"((r)[0]), "=r"((r)[1]), "=r"((r)[2]), "=r"((r)[3]) : "r"(addr))

#define MMA16816(d, a, b) \
    asm volatile("mma.sync.aligned.m16n8k16.row.col.f32.bf16.bf16.f32 " \
                 "{%0,%1,%2,%3},{%4,%5,%6,%7},{%8,%9},{%0,%1,%2,%3};" \
                 : "+f"((d)[0]), "+f"((d)[1]), "+f"((d)[2]), "+f"((d)[3]) \
                 : "r"((a)[0]), "r"((a)[1]), "r"((a)[2]), "r"((a)[3]), \
                   "r"((b)[0]), "r"((b)[1]))

// smem layout (bytes):
//   [0, 36864): four 9216B warp chunks: sAh bf16[32][72] @ +0, sAl @ +4608
//   [36864, 55296): sW bf16 [hi 64x72 | lo 64x72], row-major [k][n], staged once
#define WCHUNK 9216
#define DSMEM_BYTES 55296

// ---------------------------------------------------------------------------
template <bool SCATTER, bool FUSE_BN>
__global__ __launch_bounds__(128, 4)
void conv_mma_kernel(const float* __restrict__ x,
                     const __nv_bfloat16* __restrict__ wb,
                     const int* __restrict__ in_map,
                     const int* __restrict__ out_map,
                     float* __restrict__ H)
{
    extern __shared__ char sm[];

    const int t    = threadIdx.x;
    const int w    = t >> 5;
    const int lane = t & 31;

    __nv_bfloat16* sAh = reinterpret_cast<__nv_bfloat16*>(sm + w * WCHUNK);
    __nv_bfloat16* sAl = sAh + 32 * 72;

    const int ky = SCATTER ? blockIdx.y : 0;
    const int o  = SCATTER ? (ky < 13 ? ky : ky + 1) : 13;

    // Stage W_o once per block (hi+lo, stride 72 = 144B rows, 18432 B)
    {
        const uint4* src = reinterpret_cast<const uint4*>(wb + (size_t)o * 9216);
        uint4*       dst = reinterpret_cast<uint4*>(sm + 36864);
#pragma unroll
        for (int i = 0; i < 9; i++) dst[t + i * 128] = src[t + i * 128];
    }
    __syncthreads();   // only block barrier

    const uint32_t aAh = (uint32_t)__cvta_generic_to_shared(sAh);
    const uint32_t aAl = (uint32_t)__cvta_generic_to_shared(sAl);
    const uint32_t aW  = (uint32_t)__cvta_generic_to_shared(sm + 36864);

    // gather mapping: 8 lanes per row -> 4 rows per warp instruction
    const int rsub = lane >> 3;       // 0..3
    const int c8   = lane & 7;        // float4-pair column (8 floats)

    float4 sc0, sc1, sb0, sb1;
    if (FUSE_BN) {
        sc0 = *reinterpret_cast<const float4*>(&g_coef[c8 * 8]);
        sc1 = *reinterpret_cast<const float4*>(&g_coef[c8 * 8 + 4]);
        sb0 = *reinterpret_cast<const float4*>(&g_coef[64 + c8 * 8]);
        sb1 = *reinterpret_cast<const float4*>(&g_coef[64 + c8 * 8 + 4]);
    }

    for (int tt = 0; tt < TILES; tt++) {
        const int base = (blockIdx.x * TILES + tt) * 128;
        if (!SCATTER && base >= N_VOX) break;

        int myrow, myorow;
        if (SCATTER) {
            const size_t kbase = (size_t)ky * PP + base;
            if (__ldg(&in_map[kbase]) >= N_VOX) break;   // tail-packed sentinels
            myrow  = __ldg(&in_map[kbase + t]);
            myorow = __ldg(&out_map[kbase + t]);
        }

        // ---- Gather (+ fused BN1+ReLU) + bf16 hi/lo split, STS.128 ----
        {
            const float4* x4 = reinterpret_cast<const float4*>(x);
#pragma unroll
            for (int j = 0; j < 8; j++) {
                const int rl  = j * 4 + rsub;     // local row 0..31
                const int row = SCATTER ? __shfl_sync(0xffffffffu, myrow, rl)
                                        : (base + w * 32 + rl);
                float4 v0 = make_float4(0.f, 0.f, 0.f, 0.f), v1 = v0;
                if (row < N_VOX) {
                    v0 = x4[(size_t)row * 16 + c8 * 2];
                    v1 = x4[(size_t)row * 16 + c8 * 2 + 1];
                }
                if (FUSE_BN) {
                    v0.x = fmaxf(fmaf(v0.x, sc0.x, sb0.x), 0.f);
                    v0.y = fmaxf(fmaf(v0.y, sc0.y, sb0.y), 0.f);
                    v0.z = fmaxf(fmaf(v0.z, sc0.z, sb0.z), 0.f);
                    v0.w = fmaxf(fmaf(v0.w, sc0.w, sb0.w), 0.f);
                    v1.x = fmaxf(fmaf(v1.x, sc1.x, sb1.x), 0.f);
                    v1.y = fmaxf(fmaf(v1.y, sc1.y, sb1.y), 0.f);
                    v1.z = fmaxf(fmaf(v1.z, sc1.z, sb1.z), 0.f);
                    v1.w = fmaxf(fmaf(v1.w, sc1.w, sb1.w), 0.f);
                }
                union { __nv_bfloat16 b[8]; uint4 u; } hi, lo;
                hi.b[0] = __float2bfloat16(v0.x); hi.b[1] = __float2bfloat16(v0.y);
                hi.b[2] = __float2bfloat16(v0.z); hi.b[3] = __float2bfloat16(v0.w);
                hi.b[4] = __float2bfloat16(v1.x); hi.b[5] = __float2bfloat16(v1.y);
                hi.b[6] = __float2bfloat16(v1.z); hi.b[7] = __float2bfloat16(v1.w);
                lo.b[0] = __float2bfloat16(v0.x - __bfloat162float(hi.b[0]));
                lo.b[1] = __float2bfloat16(v0.y - __bfloat162float(hi.b[1]));
                lo.b[2] = __float2bfloat16(v0.z - __bfloat162float(hi.b[2]));
                lo.b[3] = __float2bfloat16(v0.w - __bfloat162float(hi.b[3]));
                lo.b[4] = __float2bfloat16(v1.x - __bfloat162float(hi.b[4]));
                lo.b[5] = __float2bfloat16(v1.y - __bfloat162float(hi.b[5]));
                lo.b[6] = __float2bfloat16(v1.z - __bfloat162float(hi.b[6]));
                lo.b[7] = __float2bfloat16(v1.w - __bfloat162float(hi.b[7]));
                *reinterpret_cast<uint4*>(sAh + rl * 72 + c8 * 8) = hi.u;
                *reinterpret_cast<uint4*>(sAl + rl * 72 + c8 * 8) = lo.u;
            }
        }
        __syncwarp();   // cross-lane STS -> ldmatrix visibility

        // ---- mma.sync: this warp's 32 rows x 64 cols, 3-pass bf16 hi/lo ----
        float acc[2][8][4];
#pragma unroll
        for (int mt = 0; mt < 2; mt++)
#pragma unroll
            for (int nt = 0; nt < 8; nt++)
#pragma unroll
                for (int i = 0; i < 4; i++) acc[mt][nt][i] = 0.f;

#pragma unroll
        for (int ks = 0; ks < 4; ks++) {
            // B: one x4.trans per nt fetches bh{0,1} + bl{0,1}
            uint32_t bhl[8][4];
            const uint32_t brow = aW + (ks * 16 + (lane & 15)) * 144
                                  + ((lane & 16) ? 9216u : 0u);
#pragma unroll
            for (int nt = 0; nt < 8; nt++)
                LDMB4T(bhl[nt], brow + nt * 16);

#pragma unroll
            for (int mt = 0; mt < 2; mt++) {
                const uint32_t arow = (mt * 16 + (lane & 15)) * 144
                                      + ks * 32 + ((lane >> 4) << 4);
                uint32_t ah[4], al[4];
                LDMA4(ah, aAh + arow);
                LDMA4(al, aAl + arow);
#pragma unroll
                for (int nt = 0; nt < 8; nt++) {
                    MMA16816(acc[mt][nt], ah, &bhl[nt][0]);
                    MMA16816(acc[mt][nt], ah, &bhl[nt][2]);
                    MMA16816(acc[mt][nt], al, &bhl[nt][0]);
                }
            }
        }
        __syncwarp();   // ldmatrix reads done before next tile's gather STS

        // ---- Epilogue DIRECT from acc regs ----
        const int rq = lane >> 2;
        const int cb = (lane & 3) * 2;
#pragma unroll
        for (int mt = 0; mt < 2; mt++) {
            const int rl1 = mt * 16 + rq;
            const int rl2 = rl1 + 8;
            int o1, o2;
            if (SCATTER) {
                o1 = __shfl_sync(0xffffffffu, myorow, rl1);
                o2 = __shfl_sync(0xffffffffu, myorow, rl2);
            } else {
                o1 = base + w * 32 + rl1;
                o2 = base + w * 32 + rl2;
            }
            if (o1 < N_VOX) {
                float* d = H + (size_t)o1 * 64 + cb;
                if (SCATTER) {
#pragma unroll
                    for (int nt = 0; nt < 8; nt++)
                        RED2(d + nt * 8, acc[mt][nt][0], acc[mt][nt][1]);
                } else {
#pragma unroll
                    for (int nt = 0; nt < 8; nt++)
                        *reinterpret_cast<float2*>(d + nt * 8) =
                            make_float2(acc[mt][nt][0], acc[mt][nt][1]);
                }
            }
            if (o2 < N_VOX) {
                float* d = H + (size_t)o2 * 64 + cb;
                if (SCATTER) {
#pragma unroll
                    for (int nt = 0; nt < 8; nt++)
                        RED2(d + nt * 8, acc[mt][nt][2], acc[mt][nt][3]);
                } else {
#pragma unroll
                    for (int nt = 0; nt < 8; nt++)
                        *reinterpret_cast<float2*>(d + nt * 8) =
                            make_float2(acc[mt][nt][2], acc[mt][nt][3]);
                }
            }
        }
    }
}

// ---------------------------------------------------------------------------
// W prep: bf16 hi/lo split into padded [27][2][64(k)][72(n)]
__global__ void wprep_kernel(const float* __restrict__ W)
{
    const int o = blockIdx.x;
    const int t = threadIdx.x;   // 128
    for (int idx = t; idx < 4608; idx += 128) {
        const int k = idx / 72, n = idx % 72;
        float v = (n < 64) ? W[(size_t)o * 4096 + k * 64 + n] : 0.f;
        __nv_bfloat16 hi = __float2bfloat16(v);
        __nv_bfloat16 lo = __float2bfloat16(v - __bfloat162float(hi));
        g_wb[(size_t)o * 9216 + idx]        = hi;
        g_wb[(size_t)o * 9216 + 4608 + idx] = lo;
    }
}

// ---------------------------------------------------------------------------
__global__ void zero_stats_kernel() { g_stats[threadIdx.x] = 0.f; }

__global__ void stats_kernel(const float* __restrict__ h, int statoff)
{
    const int t = threadIdx.x;          // 256
    const int ch = t & 63;
    const int g  = t >> 6;
    float s = 0.f, sq = 0.f;
#pragma unroll 4
    for (int row = blockIdx.x * 4 + g; row < N_VOX; row += gridDim.x * 4) {
        float v = h[(size_t)row * 64 + ch];
        s += v; sq = fmaf(v, v, sq);
    }
    __shared__ float sh[2][4][64];
    sh[0][g][ch] = s;
    sh[1][g][ch] = sq;
    __syncthreads();
    if (t < 64) {
        float ss = sh[0][0][t] + sh[0][1][t] + sh[0][2][t] + sh[0][3][t];
        atomicAdd(&g_stats[statoff + t], ss);
    } else if (t < 128) {
        int c = t - 64;
        float qq = sh[1][0][c] + sh[1][1][c] + sh[1][2][c] + sh[1][3][c];
        atomicAdd(&g_stats[statoff + 64 + c], qq);
    }
}

__global__ void finalize_stats_kernel(const float* __restrict__ gamma,
                                      const float* __restrict__ beta,
                                      int statoff, int coefoff)
{
    const int c = threadIdx.x;  // 64
    const float inv_n = 1.0f / (float)N_VOX;
    float mu  = g_stats[statoff + c] * inv_n;
    float var = g_stats[statoff + 64 + c] * inv_n - mu * mu;
    float sc  = gamma[c] * rsqrtf(var + EPSV);
    g_coef[coefoff + c]      = sc;
    g_coef[coefoff + 64 + c] = beta[c] - mu * sc;
}

// out = relu(bn2(h2) + x)
__global__ void final_kernel(const float* __restrict__ h2,
                             const float* __restrict__ x,
                             float* __restrict__ out, int coefoff)
{
    int kk = blockIdx.x * blockDim.x + threadIdx.x;
    if (kk >= N_VOX * 16) return;
    int cb = (kk & 15) * 4;
    float4 v = reinterpret_cast<const float4*>(h2)[kk];
    float4 r = reinterpret_cast<const float4*>(x)[kk];
    float s0 = g_coef[coefoff + cb + 0], b0 = g_coef[coefoff + 64 + cb + 0];
    float s1 = g_coef[coefoff + cb + 1], b1 = g_coef[coefoff + 64 + cb + 1];
    float s2 = g_coef[coefoff + cb + 2], b2 = g_coef[coefoff + 64 + cb + 2];
    float s3 = g_coef[coefoff + cb + 3], b3 = g_coef[coefoff + 64 + cb + 3];
    v.x = fmaxf(fmaf(v.x, s0, b0) + r.x, 0.f);
    v.y = fmaxf(fmaf(v.y, s1, b1) + r.y, 0.f);
    v.z = fmaxf(fmaf(v.z, s2, b2) + r.z, 0.f);
    v.w = fmaxf(fmaf(v.w, s3, b3) + r.w, 0.f);
    reinterpret_cast<float4*>(out)[kk] = v;
}

// ---------------------------------------------------------------------------
extern "C" void kernel_launch(void* const* d_in, const int* in_sizes, int n_in,
                              void* d_out, int out_size)
{
    const float* x      = (const float*)d_in[0];
    const float* W1     = (const float*)d_in[1];
    const float* gamma1 = (const float*)d_in[2];
    const float* beta1  = (const float*)d_in[3];
    const float* W2     = (const float*)d_in[4];
    const float* gamma2 = (const float*)d_in[5];
    const float* beta2  = (const float*)d_in[6];
    const int*   in_map = (const int*)d_in[7];
    const int*   out_map= (const int*)d_in[8];
    float*       out    = (float*)d_out;

    float* h1;  cudaGetSymbolAddress((void**)&h1, g_h1);
    float* h2;  cudaGetSymbolAddress((void**)&h2, g_h2);
    __nv_bfloat16* wb;  cudaGetSymbolAddress((void**)&wb, g_wb);

    cudaFuncSetAttribute(conv_mma_kernel<true, false>,
                         cudaFuncAttributeMaxDynamicSharedMemorySize, DSMEM_BYTES);
    cudaFuncSetAttribute(conv_mma_kernel<false, false>,
                         cudaFuncAttributeMaxDynamicSharedMemorySize, DSMEM_BYTES);
    cudaFuncSetAttribute(conv_mma_kernel<true, true>,
                         cudaFuncAttributeMaxDynamicSharedMemorySize, DSMEM_BYTES);
    cudaFuncSetAttribute(conv_mma_kernel<false, true>,
                         cudaFuncAttributeMaxDynamicSharedMemorySize, DSMEM_BYTES);

    const dim3 scat_grid(PP / (128 * TILES), 26);
    const int  center_blocks = (N_VOX + 128 * TILES - 1) / (128 * TILES);
    const int  ew_blocks     = (N_VOX * 16 + 255) / 256;

    zero_stats_kernel<<<1, 256>>>();

    // conv1 (raw x)
    wprep_kernel<<<27, 128>>>(W1);
    conv_mma_kernel<false, false><<<center_blocks, 128, DSMEM_BYTES>>>(x, wb, nullptr, nullptr, h1);
    conv_mma_kernel<true,  false><<<scat_grid,     128, DSMEM_BYTES>>>(x, wb, in_map, out_map, h1);
    stats_kernel<<<1024, 256>>>(h1, 0);
    finalize_stats_kernel<<<1, 64>>>(gamma1, beta1, 0, 0);

    // conv2: BN1+ReLU fused into the gather (h1 stays raw)
    wprep_kernel<<<27, 128>>>(W2);
    conv_mma_kernel<false, true><<<center_blocks, 128, DSMEM_BYTES>>>(h1, wb, nullptr, nullptr, h2);
    conv_mma_kernel<true,  true><<<scat_grid,     128, DSMEM_BYTES>>>(h1, wb, in_map, out_map, h2);
    stats_kernel<<<1024, 256>>>(h2, 128);
    finalize_stats_kernel<<<1, 64>>>(gamma2, beta2, 128, 128);

    // bn2 + residual + relu -> d_out
    final_kernel<<<ew_blocks, 256>>>(h2, x, out, 128);
}